// round 1
// baseline (speedup 1.0000x reference)
#include <cuda_runtime.h>
#include <cstdint>
#include <math.h>

// Problem dims (fixed by the dataset)
#define T_STEPS 64
#define BATCH   64
#define HID     1024
#define EMB     1024
#define VOC     32000
#define NL      2
#define M2      (NL*BATCH)        // 128 stacked state rows
#define TB      (T_STEPS*BATCH)   // 4096

// ---------------- device scratch (no cudaMalloc allowed) ----------------
__device__ float g_xpre[(size_t)TB * 3 * HID];   // [t*B+b][r|f|h] layer-0 input projections (+bias)
__device__ float g_h1hist[(size_t)TB * HID];     // h[1] per step, decoder input
__device__ float g_h[M2 * HID];                  // stacked state [l'*B+b][H]
__device__ float g_rh[M2 * HID];                 // r * h
__device__ float g_f[M2 * HID];                  // f gate
__device__ float g_xh[M2 * HID];                 // layer-1 x@Wh1 + bh1 staging
__device__ float g_WUr1[HID * HID];              // Wr[1] + Ur[1]
__device__ float g_WUf1[HID * HID];              // Wf[1] + Uf[1]

__device__ __forceinline__ float sigm(float x) { return 1.0f / (1.0f + expf(-x)); }

// ---------------- generic register-tiled SGEMM core ----------------
// Computes acc += A_tile @ W_tile.T where A is [M,K] row-major, W is [N,K] row-major.
// lda == ldw == K for every matrix in this problem.
template<int BM, int BN, int BK, int TM, int TN>
struct Core {
    static constexpr int NTH = (BM / TM) * (BN / TN);
    static_assert(BM * BK / 4 == NTH, "A loader mapping");
    static_assert(BN * BK / 4 == NTH, "W loader mapping");

    // a_ptr: &A[m0 + a_m][a_k]   w_ptr: &W[n0 + w_n][w_k]  (thread-specific, precomputed by caller)
    __device__ static void run(const float* __restrict__ a_ptr,
                               const float* __restrict__ w_ptr,
                               int K, float (&acc)[TM][TN],
                               float* As, float* Ws)
    {
        const int tid = threadIdx.x;
        constexpr int KV = BK / 4;
        const int a_m = tid / KV, a_k = (tid % KV) * 4;
        const int w_n = a_m,      w_k = a_k;
        const int tn = tid % (BN / TN), tm = tid / (BN / TN);

        float4 av = *(const float4*)a_ptr;
        float4 wv = *(const float4*)w_ptr;

        for (int kt = 0; kt < K; kt += BK) {
            __syncthreads();
            As[(a_k+0)*BM + a_m] = av.x; As[(a_k+1)*BM + a_m] = av.y;
            As[(a_k+2)*BM + a_m] = av.z; As[(a_k+3)*BM + a_m] = av.w;
            Ws[(w_k+0)*BN + w_n] = wv.x; Ws[(w_k+1)*BN + w_n] = wv.y;
            Ws[(w_k+2)*BN + w_n] = wv.z; Ws[(w_k+3)*BN + w_n] = wv.w;
            __syncthreads();
            if (kt + BK < K) {  // prefetch next k-tile while computing
                av = *(const float4*)(a_ptr + kt + BK);
                wv = *(const float4*)(w_ptr + kt + BK);
            }
            #pragma unroll
            for (int k = 0; k < BK; k++) {
                float af[TM], wf[TN];
                #pragma unroll
                for (int i = 0; i < TM; i++) af[i] = As[k*BM + tm*TM + i];
                #pragma unroll
                for (int j = 0; j < TN; j++) wf[j] = Ws[k*BN + tn*TN + j];
                #pragma unroll
                for (int i = 0; i < TM; i++)
                    #pragma unroll
                    for (int j = 0; j < TN; j++)
                        acc[i][j] = fmaf(af[i], wf[j], acc[i][j]);
            }
        }
    }
};

// ---------------- setup kernels ----------------
__global__ void k_hinit(const float* __restrict__ hidden) {
    int i = blockIdx.x * blockDim.x + threadIdx.x;
    if (i < M2 * HID) g_h[i] = hidden[i];
}

__global__ void k_hout(float* __restrict__ out) {
    int i = blockIdx.x * blockDim.x + threadIdx.x;
    if (i < M2 * HID) out[i] = g_h[i];
}

__global__ void k_addw(const float* __restrict__ Wr1, const float* __restrict__ Ur1,
                       const float* __restrict__ Wf1, const float* __restrict__ Uf1) {
    int i = blockIdx.x * blockDim.x + threadIdx.x;
    if (i < HID * HID) {
        g_WUr1[i] = Wr1[i] + Ur1[i];
        g_WUf1[i] = Wf1[i] + Uf1[i];
    }
}

// ---------------- precompute: xpre = gather(emb) @ [Wr0|Wf0|Wh0].T + bias ----------------
__global__ __launch_bounds__(256)
void k_pre(const int* __restrict__ tokens, const float* __restrict__ emb,
           const float* __restrict__ W0, const float* __restrict__ W1, const float* __restrict__ W2,
           const float* __restrict__ b0, const float* __restrict__ b1, const float* __restrict__ b2)
{
    constexpr int BM = 128, BN = 128, BK = 8, TM = 8, TN = 8;
    __shared__ float As[BK*BM], Ws[BK*BN];
    const int m0 = blockIdx.y * BM, n0 = blockIdx.x * BN;
    const int seg = n0 >> 10, nn0 = n0 & 1023;
    const float* W    = (seg == 0) ? W0 : (seg == 1) ? W1 : W2;
    const float* bias = (seg == 0) ? b0 : (seg == 1) ? b1 : b2;

    const int tid = threadIdx.x;
    constexpr int KV = BK / 4;
    const int a_m = tid / KV, a_k = (tid % KV) * 4;
    const int tok = tokens[m0 + a_m];

    float acc[TM][TN] = {};
    Core<BM,BN,BK,TM,TN>::run(emb + (size_t)tok * EMB + a_k,
                              W + (size_t)(nn0 + a_m) * HID + a_k,
                              HID, acc, As, Ws);

    const int tn = tid % (BN/TN), tm = tid / (BN/TN);
    #pragma unroll
    for (int i = 0; i < TM; i++) {
        const int m = m0 + tm*TM + i;
        #pragma unroll
        for (int j = 0; j < TN; j++) {
            const int n = n0 + tn*TN + j;
            const int nn = nn0 + tn*TN + j;
            g_xpre[(size_t)m * (3*HID) + n] = acc[i][j] + bias[nn];
        }
    }
}

// ---------------- per-step kernels (BM=64,BN=64,BK=16,TM=TN=4) ----------------
__global__ __launch_bounds__(256)
void k_gates0(int t, const float* __restrict__ Ur0, const float* __restrict__ Uf0,
              const float* __restrict__ bur0, const float* __restrict__ buf0)
{
    constexpr int BM = 64, BN = 64, BK = 16, TM = 4, TN = 4;
    __shared__ float As[BK*BM], Ws[BK*BN];
    const int m0 = blockIdx.y * BM, n0 = blockIdx.x * BN;
    const int seg = n0 >> 10, nn0 = n0 & 1023;
    const float* W    = seg ? Uf0 : Ur0;
    const float* bias = seg ? buf0 : bur0;

    const int tid = threadIdx.x;
    constexpr int KV = BK / 4;
    const int a_m = tid / KV, a_k = (tid % KV) * 4;

    float acc[TM][TN] = {};
    Core<BM,BN,BK,TM,TN>::run(g_h + (size_t)(m0 + a_m) * HID + a_k,
                              W + (size_t)(nn0 + a_m) * HID + a_k,
                              HID, acc, As, Ws);

    const int tn = tid % (BN/TN), tm = tid / (BN/TN);
    #pragma unroll
    for (int i = 0; i < TM; i++) {
        const int m = m0 + tm*TM + i;
        const int b = m & (BATCH - 1);
        #pragma unroll
        for (int j = 0; j < TN; j++) {
            const int n = n0 + tn*TN + j;        // 0..2047 aligns with xpre [r|f] segments
            const int nn = nn0 + tn*TN + j;
            const float xadd = g_xpre[((size_t)t * BATCH + b) * (3*HID) + n];
            const float v = sigm(acc[i][j] + bias[nn] + xadd);
            const int idx = m * HID + nn;
            if (seg == 0) g_rh[idx] = v * g_h[idx];
            else          g_f[idx] = v;
        }
    }
}

__global__ __launch_bounds__(256)
void k_hwup0(int t, const float* __restrict__ Uh0, const float* __restrict__ buh0)
{
    constexpr int BM = 64, BN = 64, BK = 16, TM = 4, TN = 4;
    __shared__ float As[BK*BM], Ws[BK*BN];
    const int m0 = blockIdx.y * BM, n0 = blockIdx.x * BN;
    const int tid = threadIdx.x;
    constexpr int KV = BK / 4;
    const int a_m = tid / KV, a_k = (tid % KV) * 4;

    float acc[TM][TN] = {};
    Core<BM,BN,BK,TM,TN>::run(g_rh + (size_t)(m0 + a_m) * HID + a_k,
                              Uh0 + (size_t)(n0 + a_m) * HID + a_k,
                              HID, acc, As, Ws);

    const int tn = tid % (BN/TN), tm = tid / (BN/TN);
    #pragma unroll
    for (int i = 0; i < TM; i++) {
        const int m = m0 + tm*TM + i;
        const int b = m & (BATCH - 1);
        #pragma unroll
        for (int j = 0; j < TN; j++) {
            const int n = n0 + tn*TN + j;
            const float xadd = g_xpre[((size_t)t * BATCH + b) * (3*HID) + 2*HID + n];
            const float hw = tanhf(acc[i][j] + buh0[n] + xadd);
            const int idx = m * HID + n;
            const float f = g_f[idx], h = g_h[idx];
            g_h[idx] = h + f * (hw - h);
        }
    }
}

__global__ __launch_bounds__(256)
void k_gates1(const float* __restrict__ Wh1,
              const float* __restrict__ br1, const float* __restrict__ bur1,
              const float* __restrict__ bf1, const float* __restrict__ buf1,
              const float* __restrict__ bh1)
{
    constexpr int BM = 64, BN = 64, BK = 16, TM = 4, TN = 4;
    __shared__ float As[BK*BM], Ws[BK*BN];
    const int m0 = blockIdx.y * BM, n0 = blockIdx.x * BN;
    const int seg = n0 >> 10, nn0 = n0 & 1023;
    const float* W = (seg == 0) ? g_WUr1 : (seg == 1) ? g_WUf1 : Wh1;

    const int tid = threadIdx.x;
    constexpr int KV = BK / 4;
    const int a_m = tid / KV, a_k = (tid % KV) * 4;

    float acc[TM][TN] = {};
    Core<BM,BN,BK,TM,TN>::run(g_h + (size_t)(m0 + a_m) * HID + a_k,
                              W + (size_t)(nn0 + a_m) * HID + a_k,
                              HID, acc, As, Ws);

    const int tn = tid % (BN/TN), tm = tid / (BN/TN);
    #pragma unroll
    for (int i = 0; i < TM; i++) {
        const int m = m0 + tm*TM + i;
        #pragma unroll
        for (int j = 0; j < TN; j++) {
            const int nn = nn0 + tn*TN + j;
            const int idx = m * HID + nn;
            if (seg == 0) {
                const float v = sigm(acc[i][j] + br1[nn] + bur1[nn]);
                g_rh[idx] = v * g_h[idx];
            } else if (seg == 1) {
                g_f[idx] = sigm(acc[i][j] + bf1[nn] + buf1[nn]);
            } else {
                g_xh[idx] = acc[i][j] + bh1[nn];
            }
        }
    }
}

__global__ __launch_bounds__(256)
void k_hwup1(int t, const float* __restrict__ Uh1, const float* __restrict__ buh1)
{
    constexpr int BM = 64, BN = 64, BK = 16, TM = 4, TN = 4;
    __shared__ float As[BK*BM], Ws[BK*BN];
    const int m0 = blockIdx.y * BM, n0 = blockIdx.x * BN;
    const int tid = threadIdx.x;
    constexpr int KV = BK / 4;
    const int a_m = tid / KV, a_k = (tid % KV) * 4;

    float acc[TM][TN] = {};
    Core<BM,BN,BK,TM,TN>::run(g_rh + (size_t)(m0 + a_m) * HID + a_k,
                              Uh1 + (size_t)(n0 + a_m) * HID + a_k,
                              HID, acc, As, Ws);

    const int tn = tid % (BN/TN), tm = tid / (BN/TN);
    #pragma unroll
    for (int i = 0; i < TM; i++) {
        const int m = m0 + tm*TM + i;
        #pragma unroll
        for (int j = 0; j < TN; j++) {
            const int n = n0 + tn*TN + j;
            const float hw = tanhf(acc[i][j] + buh1[n] + g_xh[m*HID + n]);
            const int idx = m * HID + n;
            const float f = g_f[idx], h = g_h[idx];
            const float nh = h + f * (hw - h);
            g_h[idx] = nh;
            if (m >= BATCH)  // stash h[1] for the decoder
                g_h1hist[((size_t)t * BATCH + (m - BATCH)) * HID + n] = nh;
        }
    }
}

// ---------------- decoder: logits = h1hist @ Wdec.T + bdec ----------------
__global__ __launch_bounds__(256)
void k_dec(const float* __restrict__ Wdec, const float* __restrict__ bdec,
           float* __restrict__ out)
{
    constexpr int BM = 128, BN = 128, BK = 8, TM = 8, TN = 8;
    __shared__ float As[BK*BM], Ws[BK*BN];
    const int m0 = blockIdx.y * BM, n0 = blockIdx.x * BN;
    const int tid = threadIdx.x;
    constexpr int KV = BK / 4;
    const int a_m = tid / KV, a_k = (tid % KV) * 4;

    float acc[TM][TN] = {};
    Core<BM,BN,BK,TM,TN>::run(g_h1hist + (size_t)(m0 + a_m) * HID + a_k,
                              Wdec + (size_t)(n0 + a_m) * HID + a_k,
                              HID, acc, As, Ws);

    const int tn = tid % (BN/TN), tm = tid / (BN/TN);
    #pragma unroll
    for (int i = 0; i < TM; i++) {
        const int m = m0 + tm*TM + i;
        #pragma unroll
        for (int j = 0; j < TN; j++) {
            const int n = n0 + tn*TN + j;
            out[(size_t)m * VOC + n] = acc[i][j] + bdec[n];
        }
    }
}

// ---------------- launch ----------------
extern "C" void kernel_launch(void* const* d_in, const int* in_sizes, int n_in,
                              void* d_out, int out_size)
{
    const int*   tokens = (const int*)  d_in[0];
    const float* hidden = (const float*)d_in[1];
    const float* emb    = (const float*)d_in[2];
    const float* Wr     = (const float*)d_in[3];
    const float* br     = (const float*)d_in[4];
    const float* Wf     = (const float*)d_in[5];
    const float* bf     = (const float*)d_in[6];
    const float* Wh     = (const float*)d_in[7];
    const float* bh     = (const float*)d_in[8];
    const float* Ur     = (const float*)d_in[9];
    const float* bur    = (const float*)d_in[10];
    const float* Ufw    = (const float*)d_in[11];
    const float* bufw   = (const float*)d_in[12];
    const float* Uh     = (const float*)d_in[13];
    const float* buh    = (const float*)d_in[14];
    const float* Wdec   = (const float*)d_in[15];
    const float* bdec   = (const float*)d_in[16];
    float* out = (float*)d_out;

    const size_t HH = (size_t)HID * HID;

    k_hinit<<<(M2*HID + 1023) / 1024, 1024>>>(hidden);
    k_addw<<<(HID*HID + 255) / 256, 256>>>(Wr + HH, Ur + HH, Wf + HH, Ufw + HH);
    k_pre<<<dim3(3*HID/128, TB/128), 256>>>(tokens, emb, Wr, Wf, Wh, br, bf, bh);

    for (int t = 0; t < T_STEPS; t++) {
        k_gates0<<<dim3(2*HID/64, M2/64), 256>>>(t, Ur, Ufw, bur, bufw);
        k_hwup0 <<<dim3(HID/64,   M2/64), 256>>>(t, Uh, buh);
        k_gates1<<<dim3(3*HID/64, M2/64), 256>>>(Wh + HH, br + HID, bur + HID,
                                                 bf + HID, bufw + HID, bh + HID);
        k_hwup1 <<<dim3(HID/64,   M2/64), 256>>>(t, Uh + HH, buh + HID);
    }

    k_dec<<<dim3(VOC/128, TB/128), 256>>>(Wdec, bdec, out);

    const long long logits_elems = (long long)TB * VOC;
    if ((long long)out_size >= logits_elems + (long long)M2 * HID)
        k_hout<<<(M2*HID + 1023) / 1024, 1024>>>(out + logits_elems);
}